// round 2
// baseline (speedup 1.0000x reference)
#include <cuda_runtime.h>
#include <math.h>

#define VOCAB   267735
#define ROWS    512          // SEQ*BSZ = 128*4
#define DPROJ   1024

// cluster layout in the output vocab axis
// c0: [0,20000)      n=20000, d_emb=1024
// c1: [20000,40000)  n=20000, d_emb=256
// c2: [40000,200000) n=160000, d_emb=64
// c3: [200000,267735) n=67735, d_emb=16

// ---------------- scratch (no allocation allowed) ----------------
#define O_Y0   0
#define O_Y1   (O_Y0 + ROWS*1024)
#define O_Y2   (O_Y1 + ROWS*256)
#define O_Y3   (O_Y2 + ROWS*64)
#define O_CL   (O_Y3 + ROWS*16)
#define O_LSE  (O_CL + ROWS*3)
#define SCRATCH_FLOATS (O_LSE + ROWS*4)

__device__ float g_scratch[SCRATCH_FLOATS];

// ---------------- fast exp (FMA-only, avoids MUFU bottleneck) ----------------
// valid for x <= 0 (we only ever exponentiate (x - max) <= 0)
__device__ __forceinline__ float fast_exp_neg(float x) {
    x = fmaxf(x, -87.0f);
    float y = x * 1.4426950408889634f;   // log2(e)
    float n = rintf(y);
    float f = y - n;                      // [-0.5, 0.5]
    float t = f * 0.6931471805599453f;    // ln2 -> |t| <= 0.347
    float p = 1.0f + t*(1.0f + t*(0.5f + t*(0.16666667f + t*(0.041666667f + t*0.008333333f))));
    int ni = (int)n;                      // n in [-126, 0]
    float s = __int_as_float((ni + 127) << 23);
    return p * s;
}

// ---------------- generic tiled SGEMM: C[M,N] = A[M,K] * B[N,K]^T + bias ----------------
__global__ void sgemm_tn(const float* __restrict__ A, int lda,
                         const float* __restrict__ B, int ldb,
                         float* __restrict__ C, long ldc, long cofs,
                         const float* __restrict__ bias,
                         int M, int N, int K)
{
    __shared__ __align__(16) float As[16][68];
    __shared__ __align__(16) float Bs[16][68];
    const int tid = threadIdx.x;           // 256 threads
    const int tx = tid & 15, ty = tid >> 4;
    const int bm = blockIdx.y * 64, bn = blockIdx.x * 64;
    const int c  = tid & 15;                // k-within-tile for loads
    const int r0 = tid >> 4;                // row base for loads

    float acc[4][4] = {};

    for (int k0 = 0; k0 < K; k0 += 16) {
        #pragma unroll
        for (int p = 0; p < 4; p++) {
            int r  = r0 + p * 16;
            int gm = bm + r;
            int gn = bn + r;
            bool kok = (k0 + c) < K;
            As[c][r] = (gm < M && kok) ? A[(long)gm * lda + k0 + c] : 0.0f;
            Bs[c][r] = (gn < N && kok) ? B[(long)gn * ldb + k0 + c] : 0.0f;
        }
        __syncthreads();
        #pragma unroll
        for (int k = 0; k < 16; k++) {
            float4 av = *reinterpret_cast<const float4*>(&As[k][ty * 4]);
            float4 bv = *reinterpret_cast<const float4*>(&Bs[k][tx * 4]);
            float a[4] = {av.x, av.y, av.z, av.w};
            float b[4] = {bv.x, bv.y, bv.z, bv.w};
            #pragma unroll
            for (int i = 0; i < 4; i++)
                #pragma unroll
                for (int j = 0; j < 4; j++)
                    acc[i][j] = fmaf(a[i], b[j], acc[i][j]);
        }
        __syncthreads();
    }

    #pragma unroll
    for (int i = 0; i < 4; i++) {
        int row = bm + ty * 4 + i;
        if (row >= M) continue;
        #pragma unroll
        for (int j = 0; j < 4; j++) {
            int col = bn + tx * 4 + j;
            if (col >= N) continue;
            float v = acc[i][j];
            if (bias) v += bias[col];
            C[(long)row * ldc + cofs + col] = v;
        }
    }
}

// ---------------- cluster pseudo-token logits: [512,3] = y0 @ cw^T + cb ----------------
__global__ void cluster_logits_k(const float* __restrict__ y0,
                                 const float* __restrict__ cw,
                                 const float* __restrict__ cb,
                                 float* __restrict__ clog)
{
    int r = blockIdx.x;
    int t = threadIdx.x;   // 128 threads
    float s0 = 0.f, s1 = 0.f, s2 = 0.f;
    const float* yr = y0 + (long)r * 1024;
    for (int d = t; d < 1024; d += 128) {
        float yv = yr[d];
        s0 += yv * cw[d];
        s1 += yv * cw[1024 + d];
        s2 += yv * cw[2048 + d];
    }
    __shared__ float sh[3][128];
    sh[0][t] = s0; sh[1][t] = s1; sh[2][t] = s2;
    __syncthreads();
    for (int off = 64; off > 0; off >>= 1) {
        if (t < off) {
            sh[0][t] += sh[0][t + off];
            sh[1][t] += sh[1][t + off];
            sh[2][t] += sh[2][t + off];
        }
        __syncthreads();
    }
    if (t < 3) clog[r * 3 + t] = sh[t][0] + cb[t];
}

// ---------------- per-(row,cluster) online logsumexp over raw logits ----------------
__global__ void lse_k(const float* __restrict__ out,
                      const float* __restrict__ clog,
                      float* __restrict__ lse)
{
    const int starts[4] = {0, 20000, 40000, 200000};
    const int cnts[4]   = {20000, 20000, 160000, 67735};
    int r = blockIdx.x, cl = blockIdx.y, t = threadIdx.x;   // 256 threads
    const float* p = out + (long)r * VOCAB + starts[cl];
    int n = cnts[cl];

    float m = -INFINITY, s = 0.f;
    for (int i = t; i < n; i += 256) {
        float x = p[i];
        if (x > m) { s = s * fast_exp_neg(m - x) + 1.0f; m = x; }
        else       { s += fast_exp_neg(x - m); }
    }
    // head log-softmax also covers the 3 cluster pseudo-tokens
    if (cl == 0 && t < 3) {
        float x = clog[r * 3 + t];
        if (x > m) { s = s * fast_exp_neg(m - x) + 1.0f; m = x; }
        else       { s += fast_exp_neg(x - m); }
    }

    __shared__ float sm[256], ss[256];
    sm[t] = m; ss[t] = s;
    __syncthreads();
    for (int off = 128; off > 0; off >>= 1) {
        if (t < off) {
            float m1 = sm[t], m2 = sm[t + off];
            float s1 = ss[t], s2 = ss[t + off];
            float M = fmaxf(m1, m2);
            float S = 0.f;
            if (s1 > 0.f) S += s1 * fast_exp_neg(m1 - M);
            if (s2 > 0.f) S += s2 * fast_exp_neg(m2 - M);
            sm[t] = M; ss[t] = S;
        }
        __syncthreads();
    }
    if (t == 0) lse[r * 4 + cl] = sm[0] + logf(ss[0]);
}

// ---------------- finalize: out = logit - lse (+ head cluster logprob for tails) ----------------
__global__ void finalize_k(float* __restrict__ out,
                           const float* __restrict__ clog,
                           const float* __restrict__ lse)
{
    int r = blockIdx.y;
    float hl   = lse[r * 4 + 0];
    float adj0 = -hl;
    float adj1 = clog[r * 3 + 0] - hl - lse[r * 4 + 1];
    float adj2 = clog[r * 3 + 1] - hl - lse[r * 4 + 2];
    float adj3 = clog[r * 3 + 2] - hl - lse[r * 4 + 3];
    float* p = out + (long)r * VOCAB;
    int stride = gridDim.x * blockDim.x;
    for (int col = blockIdx.x * blockDim.x + threadIdx.x; col < VOCAB; col += stride) {
        float adj = col < 20000 ? adj0 : col < 40000 ? adj1 : col < 200000 ? adj2 : adj3;
        p[col] += adj;
    }
}

// ---------------- loss: -mean over 512 gathered target log-probs ----------------
__global__ void loss_k(const float* __restrict__ out,
                       const int* __restrict__ target,
                       float* __restrict__ dst)
{
    int t = threadIdx.x;   // 512 threads, 1 block
    float v = out[(long)t * VOCAB + target[t]];
    __shared__ float sh[512];
    sh[t] = v;
    __syncthreads();
    for (int off = 256; off > 0; off >>= 1) {
        if (t < off) sh[t] += sh[t + off];
        __syncthreads();
    }
    if (t == 0) *dst = -sh[0] / 512.0f;
}

// ---------------- launcher ----------------
extern "C" void kernel_launch(void* const* d_in, const int* in_sizes, int n_in,
                              void* d_out, int out_size)
{
    // ---- bind inputs by element count (robust to metadata ordering) ----
    // hidden 524288 | target 512 | cw 3072 | cb 3
    // proj0 1048576 | W0 20480000 | b0 20000 (first)
    // proj1 262144  | W1 5120000  | b1 20000 (second)
    // proj2 65536   | W2 10240000 | b2 160000
    // proj3 16384   | W3 1083760  | b3 67735
    const float *hidden = 0, *cw = 0, *cb = 0;
    const float *proj0 = 0, *proj1 = 0, *proj2 = 0, *proj3 = 0;
    const float *W0 = 0, *W1 = 0, *W2 = 0, *W3 = 0;
    const float *b0 = 0, *b1 = 0, *b2 = 0, *b3 = 0;
    const int *target = 0;

    for (int i = 0; i < n_in; i++) {
        const void* p = d_in[i];
        switch (in_sizes[i]) {
            case 524288:   hidden = (const float*)p; break;
            case 512:      target = (const int*)p;   break;
            case 3072:     cw = (const float*)p;     break;
            case 3:        cb = (const float*)p;     break;
            case 1048576:  proj0 = (const float*)p;  break;
            case 20480000: W0 = (const float*)p;     break;
            case 262144:   proj1 = (const float*)p;  break;
            case 5120000:  W1 = (const float*)p;     break;
            case 65536:    proj2 = (const float*)p;  break;
            case 10240000: W2 = (const float*)p;     break;
            case 160000:   b2 = (const float*)p;     break;
            case 16384:    proj3 = (const float*)p;  break;
            case 1083760:  W3 = (const float*)p;     break;
            case 67735:    b3 = (const float*)p;     break;
            case 20000:    if (!b0) b0 = (const float*)p; else b1 = (const float*)p; break;
            default: break;
        }
    }
    float* out = (float*)d_out;

    float* scratch = nullptr;
    cudaGetSymbolAddress((void**)&scratch, g_scratch);
    float* y0   = scratch + O_Y0;
    float* y1   = scratch + O_Y1;
    float* y2   = scratch + O_Y2;
    float* y3   = scratch + O_Y3;
    float* clog = scratch + O_CL;
    float* lse  = scratch + O_LSE;

    const int MB = (ROWS + 63) / 64;   // 8

    // projections: y_i = hidden @ proj_i^T
    sgemm_tn<<<dim3(16, MB), 256>>>(hidden, DPROJ, proj0, DPROJ, y0, 1024, 0, nullptr, ROWS, 1024, DPROJ);
    sgemm_tn<<<dim3(4,  MB), 256>>>(hidden, DPROJ, proj1, DPROJ, y1, 256,  0, nullptr, ROWS, 256,  DPROJ);
    sgemm_tn<<<dim3(1,  MB), 256>>>(hidden, DPROJ, proj2, DPROJ, y2, 64,   0, nullptr, ROWS, 64,   DPROJ);
    sgemm_tn<<<dim3(1,  MB), 256>>>(hidden, DPROJ, proj3, DPROJ, y3, 16,   0, nullptr, ROWS, 16,   DPROJ);

    // logits (written raw into d_out at the right vocab offsets)
    sgemm_tn<<<dim3((20000 + 63) / 64, MB), 256>>>(y0, 1024, W0, 1024, out, VOCAB, 0,      b0, ROWS, 20000,  1024);
    cluster_logits_k<<<ROWS, 128>>>(y0, cw, cb, clog);
    sgemm_tn<<<dim3((20000 + 63) / 64, MB), 256>>>(y1, 256,  W1, 256,  out, VOCAB, 20000,  b1, ROWS, 20000,  256);
    sgemm_tn<<<dim3(160000 / 64,       MB), 256>>>(y2, 64,   W2, 64,   out, VOCAB, 40000,  b2, ROWS, 160000, 64);
    sgemm_tn<<<dim3((67735 + 63) / 64, MB), 256>>>(y3, 16,   W3, 16,   out, VOCAB, 200000, b3, ROWS, 67735,  16);

    // per-cluster logsumexp, then convert logits -> adaptive log-probs
    lse_k<<<dim3(ROWS, 4), 256>>>(out, clog, lse);
    finalize_k<<<dim3(64, ROWS), 256>>>(out, clog, lse);

    // loss scalar appended after the [512, VOCAB] block
    long total = (long)ROWS * VOCAB;
    if ((long)out_size > total)
        loss_k<<<1, ROWS>>>(out, target, out + total);
}

// round 5
// speedup vs baseline: 1.6670x; 1.6670x over previous
#include <cuda_runtime.h>
#include <cuda_bf16.h>
#include <math.h>
#include <stdint.h>

static constexpr int VOCAB = 267735;
static constexpr int ROWS  = 512;

// bf16 scratch element offsets
static constexpr size_t B_W0 = 0;
static constexpr size_t B_W1 = 20480000;
static constexpr size_t B_W2 = 25600000;
static constexpr size_t B_W3 = 35840000;
static constexpr size_t B_P0 = 36923760;
static constexpr size_t B_P1 = 37972336;
static constexpr size_t B_P2 = 38234480;
static constexpr size_t B_P3 = 38300016;
static constexpr size_t B_H  = 38316400;
static constexpr size_t B_Y0 = 38840688;
static constexpr size_t B_Y1 = 39364976;
static constexpr size_t B_Y2 = 39496048;
static constexpr size_t B_Y3 = 39528816;
static constexpr size_t B_END = 39537008;

__device__ __align__(16) __nv_bfloat16 g_bf[B_END];
__device__ __align__(16) float g_f32[ROWS * 3 + ROWS * 4];

// ---------------- fp32 -> bf16 convert ----------------
__global__ void conv_k(const float* __restrict__ in, __nv_bfloat16* __restrict__ out, int n) {
    int i = (blockIdx.x * blockDim.x + threadIdx.x) * 4;
    if (i + 3 < n) {
        float4 v = *reinterpret_cast<const float4*>(in + i);
        __nv_bfloat162 a = __floats2bfloat162_rn(v.x, v.y);
        __nv_bfloat162 b = __floats2bfloat162_rn(v.z, v.w);
        uint2 u;
        u.x = *reinterpret_cast<uint32_t*>(&a);
        u.y = *reinterpret_cast<uint32_t*>(&b);
        *reinterpret_cast<uint2*>(out + i) = u;
    } else {
        for (int j = i; j < n; j++) out[j] = __float2bfloat16(in[j]);
    }
}

// ---------------- HMMA bf16 GEMM: C[512,N] = A[512,K] @ B[N,K]^T ----------------
// CTA tile 128x128, 8 warps (4M x 2N), warp tile 32x64, K-chunk 64.
// mma.sync.m16n8k16 row.col f32.bf16.bf16.f32.
// Cf != null: fp32 out with bias at Cf[row*ldc + cofs + col]; else bf16 to Cb[row*ldcb+col].
static constexpr int ASTRIDE = 72;   // bf16 elements per SMEM row (64 + 8 pad)

__device__ __forceinline__ void mma16816(float* c, const uint32_t* a, const uint32_t* b) {
    asm volatile(
        "mma.sync.aligned.m16n8k16.row.col.f32.bf16.bf16.f32 "
        "{%0,%1,%2,%3}, {%4,%5,%6,%7}, {%8,%9}, {%0,%1,%2,%3};"
        : "+f"(c[0]), "+f"(c[1]), "+f"(c[2]), "+f"(c[3])
        : "r"(a[0]), "r"(a[1]), "r"(a[2]), "r"(a[3]), "r"(b[0]), "r"(b[1]));
}

__global__ void __launch_bounds__(256)
gemm_bf16_k(const __nv_bfloat16* __restrict__ A,
            const __nv_bfloat16* __restrict__ B,
            int N, int K,
            float* __restrict__ Cf, long ldc, long cofs,
            const float* __restrict__ bias,
            __nv_bfloat16* __restrict__ Cb, int ldcb)
{
    __shared__ __align__(16) __nv_bfloat16 As[128 * ASTRIDE];
    __shared__ __align__(16) __nv_bfloat16 Bs[128 * ASTRIDE];

    const int tid  = threadIdx.x;
    const int wid  = tid >> 5, lane = tid & 31;
    const int wm   = wid & 3;          // 0..3 : rows [wm*32, +32)
    const int wn   = wid >> 2;         // 0..1 : cols [wn*64, +64)
    const int g    = lane >> 2;        // 0..7
    const int tg   = lane & 3;         // 0..3
    const int mt   = blockIdx.y;       // M tile (128 rows each)
    const int n0   = blockIdx.x * 128; // N tile base

    float acc[2][8][4];
    #pragma unroll
    for (int mi = 0; mi < 2; mi++)
        #pragma unroll
        for (int ni = 0; ni < 8; ni++)
            #pragma unroll
            for (int q = 0; q < 4; q++) acc[mi][ni][q] = 0.0f;

    const int nkc = (K + 63) >> 6;
    for (int kc = 0; kc < nkc; kc++) {
        const int k0 = kc << 6;
        // load A tile: 128 rows x 64 bf16 -> 1024 uint4, 256 threads x 4
        #pragma unroll
        for (int i = 0; i < 4; i++) {
            int c = tid + i * 256;
            int row = c >> 3, seg = c & 7;
            int kk = k0 + seg * 8;
            uint4 v = make_uint4(0, 0, 0, 0);
            if (kk < K) v = *reinterpret_cast<const uint4*>(A + (size_t)(mt * 128 + row) * K + kk);
            *reinterpret_cast<uint4*>(As + row * ASTRIDE + seg * 8) = v;
        }
        // load B tile: 128 n-rows x 64 bf16
        #pragma unroll
        for (int i = 0; i < 4; i++) {
            int c = tid + i * 256;
            int row = c >> 3, seg = c & 7;
            int kk = k0 + seg * 8;
            int gn = n0 + row;
            uint4 v = make_uint4(0, 0, 0, 0);
            if (gn < N && kk < K) v = *reinterpret_cast<const uint4*>(B + (size_t)gn * K + kk);
            *reinterpret_cast<uint4*>(Bs + row * ASTRIDE + seg * 8) = v;
        }
        __syncthreads();

        #pragma unroll
        for (int ks = 0; ks < 4; ks++) {
            const int kb = ks * 16;
            uint32_t afrag[2][4];
            #pragma unroll
            for (int mi = 0; mi < 2; mi++) {
                int row = wm * 32 + mi * 16 + g;
                const __nv_bfloat16* p0 = As + row * ASTRIDE + kb + tg * 2;
                const __nv_bfloat16* p1 = As + (row + 8) * ASTRIDE + kb + tg * 2;
                afrag[mi][0] = *reinterpret_cast<const uint32_t*>(p0);
                afrag[mi][1] = *reinterpret_cast<const uint32_t*>(p1);
                afrag[mi][2] = *reinterpret_cast<const uint32_t*>(p0 + 8);
                afrag[mi][3] = *reinterpret_cast<const uint32_t*>(p1 + 8);
            }
            #pragma unroll
            for (int ni = 0; ni < 8; ni++) {
                int col = wn * 64 + ni * 8 + g;
                const __nv_bfloat16* q = Bs + col * ASTRIDE + kb + tg * 2;
                uint32_t bfrag[2];
                bfrag[0] = *reinterpret_cast<const uint32_t*>(q);
                bfrag[1] = *reinterpret_cast<const uint32_t*>(q + 8);
                mma16816(acc[0][ni], afrag[0], bfrag);
                mma16816(acc[1][ni], afrag[1], bfrag);
            }
        }
        __syncthreads();
    }

    // epilogue
    #pragma unroll
    for (int mi = 0; mi < 2; mi++) {
        int row = mt * 128 + wm * 32 + mi * 16 + g;
        #pragma unroll
        for (int ni = 0; ni < 8; ni++) {
            int col = n0 + wn * 64 + ni * 8 + tg * 2;
            if (Cf != nullptr) {
                float bv0 = 0.f, bv1 = 0.f;
                if (bias != nullptr) {
                    if (col < N)     bv0 = bias[col];
                    if (col + 1 < N) bv1 = bias[col + 1];
                }
                float* d0 = Cf + (size_t)row * ldc + cofs + col;
                float* d1 = Cf + (size_t)(row + 8) * ldc + cofs + col;
                if (col < N)     { d0[0] = acc[mi][ni][0] + bv0; d1[0] = acc[mi][ni][2] + bv0; }
                if (col + 1 < N) { d0[1] = acc[mi][ni][1] + bv1; d1[1] = acc[mi][ni][3] + bv1; }
            } else {
                if (col + 1 < N || col < N) {
                    __nv_bfloat162 v0 = __floats2bfloat162_rn(acc[mi][ni][0], acc[mi][ni][1]);
                    __nv_bfloat162 v1 = __floats2bfloat162_rn(acc[mi][ni][2], acc[mi][ni][3]);
                    if (col + 1 < N) {
                        *reinterpret_cast<uint32_t*>(Cb + (size_t)row * ldcb + col) =
                            *reinterpret_cast<uint32_t*>(&v0);
                        *reinterpret_cast<uint32_t*>(Cb + (size_t)(row + 8) * ldcb + col) =
                            *reinterpret_cast<uint32_t*>(&v1);
                    } else if (col < N) {
                        Cb[(size_t)row * ldcb + col] = __low2bfloat16(v0);
                        Cb[(size_t)(row + 8) * ldcb + col] = __low2bfloat16(v1);
                    }
                }
            }
        }
    }
}

// ---------------- fast exp (FMA-only, x <= 0) ----------------
__device__ __forceinline__ float fast_exp_neg(float x) {
    x = fmaxf(x, -87.0f);
    float y = x * 1.4426950408889634f;
    float n = rintf(y);
    float f = y - n;
    float t = f * 0.6931471805599453f;
    float p = 1.0f + t*(1.0f + t*(0.5f + t*(0.16666667f + t*(0.041666667f + t*0.008333333f))));
    int ni = (int)n;
    float s = __int_as_float((ni + 127) << 23);
    return p * s;
}

// ---------------- cluster pseudo-token logits ----------------
__global__ void cluster_logits_k(const __nv_bfloat16* __restrict__ y0b,
                                 const float* __restrict__ cw,
                                 const float* __restrict__ cb,
                                 float* __restrict__ clog)
{
    int r = blockIdx.x;
    int t = threadIdx.x;   // 128
    float s0 = 0.f, s1 = 0.f, s2 = 0.f;
    const __nv_bfloat16* yr = y0b + (size_t)r * 1024;
    for (int d = t; d < 1024; d += 128) {
        float yv = __bfloat162float(yr[d]);
        s0 += yv * cw[d];
        s1 += yv * cw[1024 + d];
        s2 += yv * cw[2048 + d];
    }
    __shared__ float sh[3][128];
    sh[0][t] = s0; sh[1][t] = s1; sh[2][t] = s2;
    __syncthreads();
    for (int off = 64; off > 0; off >>= 1) {
        if (t < off) {
            sh[0][t] += sh[0][t + off];
            sh[1][t] += sh[1][t + off];
            sh[2][t] += sh[2][t + off];
        }
        __syncthreads();
    }
    if (t < 3) clog[r * 3 + t] = sh[t][0] + cb[t];
}

// ---------------- per-(row,cluster) logsumexp ----------------
__global__ void lse_k(const float* __restrict__ out,
                      const float* __restrict__ clog,
                      float* __restrict__ lse)
{
    const int starts[4] = {0, 20000, 40000, 200000};
    const int cnts[4]   = {20000, 20000, 160000, 67735};
    int r = blockIdx.x, cl = blockIdx.y, t = threadIdx.x;   // 256
    const float* p = out + (size_t)r * VOCAB + starts[cl];
    int n = cnts[cl];

    float m = -INFINITY, s = 0.f;
    for (int i = t; i < n; i += 256) {
        float x = p[i];
        if (x > m) { s = s * fast_exp_neg(m - x) + 1.0f; m = x; }
        else       { s += fast_exp_neg(x - m); }
    }
    if (cl == 0 && t < 3) {
        float x = clog[r * 3 + t];
        if (x > m) { s = s * fast_exp_neg(m - x) + 1.0f; m = x; }
        else       { s += fast_exp_neg(x - m); }
    }
    __shared__ float sm[256], ss[256];
    sm[t] = m; ss[t] = s;
    __syncthreads();
    for (int off = 128; off > 0; off >>= 1) {
        if (t < off) {
            float m1 = sm[t], m2 = sm[t + off];
            float s1 = ss[t], s2 = ss[t + off];
            float M = fmaxf(m1, m2);
            float S = 0.f;
            if (s1 > 0.f) S += s1 * fast_exp_neg(m1 - M);
            if (s2 > 0.f) S += s2 * fast_exp_neg(m2 - M);
            sm[t] = M; ss[t] = S;
        }
        __syncthreads();
    }
    if (t == 0) lse[r * 4 + cl] = sm[0] + logf(ss[0]);
}

// ---------------- finalize ----------------
__global__ void finalize_k(float* __restrict__ out,
                           const float* __restrict__ clog,
                           const float* __restrict__ lse)
{
    int r = blockIdx.y;
    float hl   = lse[r * 4 + 0];
    float adj0 = -hl;
    float adj1 = clog[r * 3 + 0] - hl - lse[r * 4 + 1];
    float adj2 = clog[r * 3 + 1] - hl - lse[r * 4 + 2];
    float adj3 = clog[r * 3 + 2] - hl - lse[r * 4 + 3];
    float* p = out + (size_t)r * VOCAB;
    int stride = gridDim.x * blockDim.x;
    for (int col = blockIdx.x * blockDim.x + threadIdx.x; col < VOCAB; col += stride) {
        float adj = col < 20000 ? adj0 : col < 40000 ? adj1 : col < 200000 ? adj2 : adj3;
        p[col] += adj;
    }
}

// ---------------- loss ----------------
__global__ void loss_k(const float* __restrict__ out,
                       const int* __restrict__ target,
                       float* __restrict__ dst)
{
    int t = threadIdx.x;
    float v = out[(size_t)t * VOCAB + target[t]];
    __shared__ float sh[512];
    sh[t] = v;
    __syncthreads();
    for (int off = 256; off > 0; off >>= 1) {
        if (t < off) sh[t] += sh[t + off];
        __syncthreads();
    }
    if (t == 0) *dst = -sh[0] / 512.0f;
}

// ---------------- launcher ----------------
extern "C" void kernel_launch(void* const* d_in, const int* in_sizes, int n_in,
                              void* d_out, int out_size)
{
    const float *hidden = 0, *cw = 0, *cb = 0;
    const float *proj0 = 0, *proj1 = 0, *proj2 = 0, *proj3 = 0;
    const float *W0 = 0, *W1 = 0, *W2 = 0, *W3 = 0;
    const float *b0 = 0, *b1 = 0, *b2 = 0, *b3 = 0;
    const int *target = 0;

    for (int i = 0; i < n_in; i++) {
        const void* p = d_in[i];
        switch (in_sizes[i]) {
            case 524288:   hidden = (const float*)p; break;
            case 512:      target = (const int*)p;   break;
            case 3072:     cw = (const float*)p;     break;
            case 3:        cb = (const float*)p;     break;
            case 1048576:  proj0 = (const float*)p;  break;
            case 20480000: W0 = (const float*)p;     break;
            case 262144:   proj1 = (const float*)p;  break;
            case 5120000:  W1 = (const float*)p;     break;
            case 65536:    proj2 = (const float*)p;  break;
            case 10240000: W2 = (const float*)p;     break;
            case 160000:   b2 = (const float*)p;     break;
            case 16384:    proj3 = (const float*)p;  break;
            case 1083760:  W3 = (const float*)p;     break;
            case 67735:    b3 = (const float*)p;     break;
            case 20000:    if (!b0) b0 = (const float*)p; else b1 = (const float*)p; break;
            default: break;
        }
    }
    float* out = (float*)d_out;

    __nv_bfloat16* bf = nullptr;
    cudaGetSymbolAddress((void**)&bf, g_bf);
    float* f32s = nullptr;
    cudaGetSymbolAddress((void**)&f32s, g_f32);
    float* clog = f32s;
    float* lse  = f32s + ROWS * 3;

    conv_k<<<20480000 / 4 / 256, 256>>>(W0, bf + B_W0, 20480000);
    conv_k<<<5120000 / 4 / 256, 256>>>(W1, bf + B_W1, 5120000);
    conv_k<<<10240000 / 4 / 256, 256>>>(W2, bf + B_W2, 10240000);
    conv_k<<<(1083760 / 4 + 255) / 256, 256>>>(W3, bf + B_W3, 1083760);
    conv_k<<<1048576 / 4 / 256, 256>>>(proj0, bf + B_P0, 1048576);
    conv_k<<<262144 / 4 / 256, 256>>>(proj1, bf + B_P1, 262144);
    conv_k<<<65536 / 4 / 256, 256>>>(proj2, bf + B_P2, 65536);
    conv_k<<<16384 / 4 / 256, 256>>>(proj3, bf + B_P3, 16384);
    conv_k<<<524288 / 4 / 256, 256>>>(hidden, bf + B_H, 524288);

    // projections: y_i(bf16) = hidden @ proj_i^T
    gemm_bf16_k<<<dim3(8, 4), 256>>>(bf + B_H, bf + B_P0, 1024, 1024,
        nullptr, 0, 0, nullptr, bf + B_Y0, 1024);
    gemm_bf16_k<<<dim3(2, 4), 256>>>(bf + B_H, bf + B_P1, 256, 1024,
        nullptr, 0, 0, nullptr, bf + B_Y1, 256);
    gemm_bf16_k<<<dim3(1, 4), 256>>>(bf + B_H, bf + B_P2, 64, 1024,
        nullptr, 0, 0, nullptr, bf + B_Y2, 64);
    gemm_bf16_k<<<dim3(1, 4), 256>>>(bf + B_H, bf + B_P3, 16, 1024,
        nullptr, 0, 0, nullptr, bf + B_Y3, 16);

    // logits into d_out
    gemm_bf16_k<<<dim3(157, 4), 256>>>(bf + B_Y0, bf + B_W0, 20000, 1024,
        out, VOCAB, 0, b0, nullptr, 0);
    cluster_logits_k<<<ROWS, 128>>>(bf + B_Y0, cw, cb, clog);
    gemm_bf16_k<<<dim3(157, 4), 256>>>(bf + B_Y1, bf + B_W1, 20000, 256,
        out, VOCAB, 20000, b1, nullptr, 0);
    gemm_bf16_k<<<dim3(1250, 4), 256>>>(bf + B_Y2, bf + B_W2, 160000, 64,
        out, VOCAB, 40000, b2, nullptr, 0);
    gemm_bf16_k<<<dim3(530, 4), 256>>>(bf + B_Y3, bf + B_W3, 67735, 16,
        out, VOCAB, 200000, b3, nullptr, 0);

    // softmax normalization + loss
    lse_k<<<dim3(ROWS, 4), 256>>>(out, clog, lse);
    finalize_k<<<dim3(64, ROWS), 256>>>(out, clog, lse);

    long total = (long)ROWS * VOCAB;
    if ((long)out_size > total)
        loss_k<<<1, ROWS>>>(out, target, out + total);
}